// round 9
// baseline (speedup 1.0000x reference)
#include <cuda_runtime.h>

#define BB 256
#define TT 1024
#define DD 128
#define LL 16
#define OO 256

// ---- recurrence geometry (R7 tiling): 256 thr = 8 warps = 4 k-chunks x 2 o-halves
// thread: 64 k-rows x 4 o-cols. 48 k in registers (24 pairs), 16 k via smem (8 pairs).
#define NTHR 256
#define RSM_TSTRIDE 272     // 32 u64 data + 2 u64 pad per thread

#define PART_OFF 0          // partial[2 parity][4 chunk][2 batch][256 o] f32 = 16 KB
#define WST_OFF  16384      // warp-private state: 8 warps x [2 batch][64 k] f32 = 4 KB
#define RSM_OFF  20480      // Rsm: 256 * 272 = 69632 B
#define SMEM_BYTES (RSM_OFF + NTHR * RSM_TSTRIDE)   // 90112 B

__device__ float g_agg[(size_t)BB * TT * OO];

// ---------------------------------------------------------------------------
// Kernel 1: agg[b,t,o] = sum_l act_l( x[b,t,:]·sub_W[l,:] + sub_b[l] ) * agg_W[l,o]
// 64 rows per CTA.
// ---------------------------------------------------------------------------
__global__ void __launch_bounds__(256) act_agg_kernel(
    const float* __restrict__ x, const float* __restrict__ subW,
    const float* __restrict__ subb, const float* __restrict__ aggW)
{
    __shared__ float xs[64][DD];
    __shared__ float ws[LL][DD + 4];
    __shared__ float as_[64][LL + 1];

    const int tid = threadIdx.x;
    const size_t row0 = (size_t)blockIdx.x * 64;

    for (int i = tid; i < LL * DD; i += 256) ws[i / DD][i % DD] = subW[i];
    {
        const float4* xg = (const float4*)(x + row0 * DD);
        float4* xs4 = (float4*)&xs[0][0];
#pragma unroll
        for (int i = 0; i < 8; i++) xs4[tid + 256 * i] = xg[tid + 256 * i];
    }
    __syncthreads();

    {
        const int l = tid & 15, rr = tid >> 4;
        const float bias = subb[l];
        const float4* wr = (const float4*)&ws[l][0];
#pragma unroll
        for (int it = 0; it < 4; it++) {
            const int r = rr + 16 * it;
            const float4* xr = (const float4*)&xs[r][0];
            float acc = 0.f;
#pragma unroll
            for (int i = 0; i < DD / 4; i++) {
                float4 a = xr[i], b = wr[i];
                acc += a.x * b.x; acc += a.y * b.y; acc += a.z * b.z; acc += a.w * b.w;
            }
            acc += bias;
            float v;
            const int m = l & 3;
            if (m == 0)      v = tanhf(acc);
            else if (m == 1) v = fmaxf(acc, 0.f);
            else if (m == 2) v = 1.f / (1.f + expf(-acc));
            else             v = acc;
            as_[r][l] = v;
        }
    }
    __syncthreads();

    {
        const int o = tid;
        float wcol[LL];
#pragma unroll
        for (int l = 0; l < LL; l++) wcol[l] = aggW[l * OO + o];
        float* outp = g_agg + row0 * OO + o;
#pragma unroll
        for (int r = 0; r < 64; r++) {
            float acc = 0.f;
#pragma unroll
            for (int l = 0; l < LL; l++) acc += as_[r][l] * wcol[l];
            outp[(size_t)r * OO] = acc;
        }
    }
}

// ---------------------------------------------------------------------------
// Kernel 2: recurrence s_t = agg_t + s_{t-1} @ R  — single barrier per step.
//   warp w (of 8): k-chunk c = w&3 (rows 64c..64c+63), o-half h = w>>2.
//   Each warp reduces its OWN next-step state chunk (redundantly with its
//   h-sibling) into a warp-private smem slot -> no second __syncthreads.
//   Partials are parity double-buffered.
// ---------------------------------------------------------------------------
#define FMA2(acc, a, b) asm("fma.rn.f32x2 %0, %1, %2, %0;" : "+l"(acc) : "l"(a), "l"(b))

__device__ __forceinline__ void lds_v2u64(unsigned long long& a, unsigned long long& b,
                                          unsigned int addr) {
    asm volatile("ld.shared.v2.u64 {%0, %1}, [%2];" : "=l"(a), "=l"(b) : "r"(addr));
}
__device__ __forceinline__ float lds_f32(unsigned int addr) {
    float v; asm volatile("ld.shared.f32 %0, [%1];" : "=f"(v) : "r"(addr)); return v;
}
__device__ __forceinline__ void sts_f32(unsigned int addr, float v) {
    asm volatile("st.shared.f32 [%0], %1;" :: "r"(addr), "f"(v));
}
__device__ __forceinline__ void sts_u64(unsigned int addr, unsigned long long v) {
    asm volatile("st.shared.u64 [%0], %1;" :: "r"(addr), "l"(v));
}

__global__ void __launch_bounds__(NTHR, 1) recur_kernel(const float* __restrict__ R,
                                                        float* __restrict__ out)
{
    extern __shared__ unsigned char dyn[];
    unsigned int sm;
    asm("{ .reg .u64 t0; cvta.to.shared.u64 t0, %1; cvt.u32.u64 %0, t0; }"
        : "=r"(sm) : "l"(dyn));

    const int tid  = threadIdx.x;
    const int lane = tid & 31;
    const int w    = tid >> 5;
    const int c    = w & 3;        // k-chunk: rows 64c .. 64c+63
    const int h    = w >> 2;       // o-half for phase-1 FMA columns
    const int b0   = blockIdx.x * 2;

    // ---- 24 k-pairs (48 rows) x 4 o-cols into registers
    unsigned long long Rp[24 * 4];
#pragma unroll
    for (int i = 0; i < 24; i++)
#pragma unroll
        for (int j = 0; j < 4; j++) {
            const int k = c * 64 + 2 * i;
            const int o = h * 128 + lane + 32 * j;
            float lo = R[(size_t)k * OO + o];
            float hi = R[(size_t)(k + 1) * OO + o];
            asm("mov.b64 %0, {%1, %2};" : "=l"(Rp[i * 4 + j]) : "f"(lo), "f"(hi));
        }

    // ---- 8 k-pairs (16 rows) x 4 o-cols into per-thread smem rows
    const unsigned int rsm = sm + RSM_OFF + tid * RSM_TSTRIDE;
#pragma unroll
    for (int i = 0; i < 8; i++)
#pragma unroll
        for (int j = 0; j < 4; j++) {
            const int k = c * 64 + 48 + 2 * i;
            const int o = h * 128 + lane + 32 * j;
            float lo = R[(size_t)k * OO + o];
            float hi = R[(size_t)(k + 1) * OO + o];
            unsigned long long p;
            asm("mov.b64 %0, {%1, %2};" : "=l"(p) : "f"(lo), "f"(hi));
            sts_u64(rsm + (unsigned)(i * 4 + j) * 8, p);
        }

    // ---- warp-private state slot: [2 batch][64 k] floats, zero-init
    const unsigned int wbase = sm + WST_OFF + w * 512;
#pragma unroll
    for (int j = 0; j < 2; j++) {
        sts_f32(wbase + 0 * 256 + (lane + 32 * j) * 4, 0.f);
        sts_f32(wbase + 1 * 256 + (lane + 32 * j) * 4, 0.f);
    }

    // phase-2 identity: this warp owns state values o' = 64c + lane + 32j (j<2), both batches
    const float* aggA = g_agg + ((size_t)b0       * TT) * OO + (c * 64 + lane);
    const float* aggB = g_agg + ((size_t)(b0 + 1) * TT) * OO + (c * 64 + lane);
    float*       outA = out   + ((size_t)b0       * TT) * OO + (c * 64 + lane);
    float*       outB = out   + ((size_t)(b0 + 1) * TT) * OO + (c * 64 + lane);

    const unsigned int pw_base = sm + PART_OFF + c * 2048 + (h * 128 + lane) * 4;
    const unsigned int pr_base = sm + PART_OFF + (c * 64 + lane) * 4;   // + par*8192 + b*1024 + j*128

    __syncthreads();

    for (int t = 0; t < TT; t++) {
        const int par = t & 1;

        // agg for this step's phase-2 (this warp's 4 state values) — latency
        // hidden under the FMA phase below. Indexed by t from fixed bases.
        const size_t trow = (size_t)t * OO;
        const float a00 = __ldg(aggA + trow);          // j=0, batch A
        const float a10 = __ldg(aggA + trow + 32);     // j=1, batch A
        const float a01 = __ldg(aggB + trow);          // j=0, batch B
        const float a11 = __ldg(aggB + trow + 32);     // j=1, batch B

        const unsigned int sA = wbase;        // batch A state chunk (warp-private)
        const unsigned int sB = wbase + 256;  // batch B

        unsigned long long acc0 = 0, acc1 = 0, acc2 = 0, acc3 = 0,
                           acc4 = 0, acc5 = 0, acc6 = 0, acc7 = 0;

        // -------- phase 1a: 24 register k-pairs --------
#pragma unroll
        for (int ii = 0; ii < 12; ii++) {
            unsigned long long ax, ay, bx, by;
            lds_v2u64(ax, ay, sA + ii * 16);
            lds_v2u64(bx, by, sB + ii * 16);
            FMA2(acc0, ax, Rp[(2*ii)*4+0]);   FMA2(acc4, bx, Rp[(2*ii)*4+0]);
            FMA2(acc1, ax, Rp[(2*ii)*4+1]);   FMA2(acc5, bx, Rp[(2*ii)*4+1]);
            FMA2(acc2, ax, Rp[(2*ii)*4+2]);   FMA2(acc6, bx, Rp[(2*ii)*4+2]);
            FMA2(acc3, ax, Rp[(2*ii)*4+3]);   FMA2(acc7, bx, Rp[(2*ii)*4+3]);
            FMA2(acc0, ay, Rp[(2*ii+1)*4+0]); FMA2(acc4, by, Rp[(2*ii+1)*4+0]);
            FMA2(acc1, ay, Rp[(2*ii+1)*4+1]); FMA2(acc5, by, Rp[(2*ii+1)*4+1]);
            FMA2(acc2, ay, Rp[(2*ii+1)*4+2]); FMA2(acc6, by, Rp[(2*ii+1)*4+2]);
            FMA2(acc3, ay, Rp[(2*ii+1)*4+3]); FMA2(acc7, by, Rp[(2*ii+1)*4+3]);
        }
        // -------- phase 1b: 8 smem k-pairs --------
#pragma unroll
        for (int qq = 0; qq < 4; qq++) {
            unsigned long long ax, ay, bx, by;
            lds_v2u64(ax, ay, sA + (12 + qq) * 16);
            lds_v2u64(bx, by, sB + (12 + qq) * 16);
            unsigned long long r0, r1, r2, r3;
            lds_v2u64(r0, r1, rsm + (2*qq) * 32);
            lds_v2u64(r2, r3, rsm + (2*qq) * 32 + 16);
            FMA2(acc0, ax, r0); FMA2(acc4, bx, r0);
            FMA2(acc1, ax, r1); FMA2(acc5, bx, r1);
            FMA2(acc2, ax, r2); FMA2(acc6, bx, r2);
            FMA2(acc3, ax, r3); FMA2(acc7, bx, r3);
            lds_v2u64(r0, r1, rsm + (2*qq+1) * 32);
            lds_v2u64(r2, r3, rsm + (2*qq+1) * 32 + 16);
            FMA2(acc0, ay, r0); FMA2(acc4, by, r0);
            FMA2(acc1, ay, r1); FMA2(acc5, by, r1);
            FMA2(acc2, ay, r2); FMA2(acc6, by, r2);
            FMA2(acc3, ay, r3); FMA2(acc7, by, r3);
        }

        // fold even/odd-k halves, store 8 partials (parity-buffered, conflict-free)
        {
            const unsigned int pw = pw_base + par * 8192;
            float x, y;
            asm("mov.b64 {%0,%1}, %2;" : "=f"(x), "=f"(y) : "l"(acc0)); sts_f32(pw + 0*1024 + 0*128, x + y);
            asm("mov.b64 {%0,%1}, %2;" : "=f"(x), "=f"(y) : "l"(acc1)); sts_f32(pw + 0*1024 + 1*128, x + y);
            asm("mov.b64 {%0,%1}, %2;" : "=f"(x), "=f"(y) : "l"(acc2)); sts_f32(pw + 0*1024 + 2*128, x + y);
            asm("mov.b64 {%0,%1}, %2;" : "=f"(x), "=f"(y) : "l"(acc3)); sts_f32(pw + 0*1024 + 3*128, x + y);
            asm("mov.b64 {%0,%1}, %2;" : "=f"(x), "=f"(y) : "l"(acc4)); sts_f32(pw + 1*1024 + 0*128, x + y);
            asm("mov.b64 {%0,%1}, %2;" : "=f"(x), "=f"(y) : "l"(acc5)); sts_f32(pw + 1*1024 + 1*128, x + y);
            asm("mov.b64 {%0,%1}, %2;" : "=f"(x), "=f"(y) : "l"(acc6)); sts_f32(pw + 1*1024 + 2*128, x + y);
            asm("mov.b64 {%0,%1}, %2;" : "=f"(x), "=f"(y) : "l"(acc7)); sts_f32(pw + 1*1024 + 3*128, x + y);
        }
        __syncthreads();   // the ONLY block-wide barrier per step

        // -------- phase 2 (per-warp, redundant with h-sibling): rebuild own chunk
        {
            const unsigned int pr = pr_base + par * 8192;
            // j=0 (o' = 64c+lane), j=1 (o' = 64c+lane+32); batches A(+0), B(+1024)
            float vA0 = a00 + lds_f32(pr)                 + lds_f32(pr + 2048)
                            + lds_f32(pr + 4096)          + lds_f32(pr + 6144);
            float vA1 = a10 + lds_f32(pr + 128)           + lds_f32(pr + 128 + 2048)
                            + lds_f32(pr + 128 + 4096)    + lds_f32(pr + 128 + 6144);
            float vB0 = a01 + lds_f32(pr + 1024)          + lds_f32(pr + 1024 + 2048)
                            + lds_f32(pr + 1024 + 4096)   + lds_f32(pr + 1024 + 6144);
            float vB1 = a11 + lds_f32(pr + 1024 + 128)        + lds_f32(pr + 1024 + 128 + 2048)
                            + lds_f32(pr + 1024 + 128 + 4096) + lds_f32(pr + 1024 + 128 + 6144);

            // publish to warp-private state slot (read only by this warp next step)
            sts_f32(wbase + 0 * 256 + lane * 4,        vA0);
            sts_f32(wbase + 0 * 256 + (lane + 32) * 4, vA1);
            sts_f32(wbase + 1 * 256 + lane * 4,        vB0);
            sts_f32(wbase + 1 * 256 + (lane + 32) * 4, vB1);

            // dedup gmem output: h==0 stores batch A, h==1 stores batch B
            if (h == 0) { outA[trow] = vA0; outA[trow + 32] = vA1; }
            else        { outB[trow] = vB0; outB[trow + 32] = vB1; }
        }
        __syncwarp();      // order cross-lane slot writes before next phase-1 reads
    }
}

// ---------------------------------------------------------------------------
extern "C" void kernel_launch(void* const* d_in, const int* in_sizes, int n_in,
                              void* d_out, int out_size)
{
    const float* x    = (const float*)d_in[0];
    const float* subW = (const float*)d_in[1];
    const float* subb = (const float*)d_in[2];
    const float* aggW = (const float*)d_in[3];
    const float* R    = (const float*)d_in[4];
    float* out = (float*)d_out;

    cudaFuncSetAttribute(recur_kernel, cudaFuncAttributeMaxDynamicSharedMemorySize,
                         SMEM_BYTES);

    act_agg_kernel<<<(BB * TT) / 64, 256>>>(x, subW, subb, aggW);
    recur_kernel<<<BB / 2, NTHR, SMEM_BYTES>>>(R, out);
}

// round 11
// speedup vs baseline: 1.4480x; 1.4480x over previous
#include <cuda_runtime.h>

#define BB 256
#define TT 1024
#define DD 128
#define LL 16
#define OO 256

// ---- recurrence geometry (R7 tiling — best measured): 256 thr = 8 warps =
// 4 k-chunks x 2 o-halves; thread: 64 k x 4 o; 48 k in regs, 16 k via smem.
#define NTHR 256
#define RSM_TSTRIDE 272     // 32 u64 data + 2 u64 pad per thread

#define PART_OFF 0          // partial[4 chunk][2 batch][256 o] f32 = 8 KB
#define S_OFF    8192       // state [2 buf][2 batch][256] f32     = 4 KB
#define RSM_OFF  12288      // Rsm: 256 * 272 = 69632 B
#define SMEM_BYTES (RSM_OFF + NTHR * RSM_TSTRIDE)   // 81920 B

// +OO pad: lets recur prefetch agg[t+1] unconditionally at t = TT-1.
__device__ float g_agg[(size_t)BB * TT * OO + OO];

#define FMA2(acc, a, b) asm("fma.rn.f32x2 %0, %1, %2, %0;" : "+l"(acc) : "l"(a), "l"(b))

__device__ __forceinline__ void lds_v2u64(unsigned long long& a, unsigned long long& b,
                                          unsigned int addr) {
    asm volatile("ld.shared.v2.u64 {%0, %1}, [%2];" : "=l"(a), "=l"(b) : "r"(addr));
}
__device__ __forceinline__ float lds_f32(unsigned int addr) {
    float v; asm volatile("ld.shared.f32 %0, [%1];" : "=f"(v) : "r"(addr)); return v;
}
__device__ __forceinline__ void sts_f32(unsigned int addr, float v) {
    asm volatile("st.shared.f32 [%0], %1;" :: "r"(addr), "f"(v));
}
__device__ __forceinline__ void sts_u64(unsigned int addr, unsigned long long v) {
    asm volatile("st.shared.u64 [%0], %1;" :: "r"(addr), "l"(v));
}

// ---------------------------------------------------------------------------
// Kernel 1: agg[b,t,o] = sum_l act_l( x[b,t,:]·sub_W[l,:] + sub_b[l] ) * agg_W[l,o]
// 64 rows per CTA. pre-dot packed f32x2 (32 ulonglong2 iters = full D=128 —
// R10 bug was 16 iters = half coverage); agg matmul with 4 o-cols/thread so
// each broadcast LDS feeds 4 FMAs.
// ---------------------------------------------------------------------------
__global__ void __launch_bounds__(256) act_agg_kernel(
    const float* __restrict__ x, const float* __restrict__ subW,
    const float* __restrict__ subb, const float* __restrict__ aggW)
{
    __shared__ float xs[64][DD];          // 32 KB  (row = 512 B, 16B-aligned)
    __shared__ float ws[LL][DD + 4];      // 8.25 KB (row stride 528 B, 16B-aligned)
    __shared__ float as_[64][LL + 1];     // 4.25 KB

    const int tid = threadIdx.x;
    const size_t row0 = (size_t)blockIdx.x * 64;

    for (int i = tid; i < LL * DD; i += 256) ws[i / DD][i % DD] = subW[i];
    {
        const float4* xg = (const float4*)(x + row0 * DD);
        float4* xs4 = (float4*)&xs[0][0];
#pragma unroll
        for (int i = 0; i < 8; i++) xs4[tid + 256 * i] = xg[tid + 256 * i];
    }
    __syncthreads();

    // ---- pre + activation: tasks (r, l), 4 rows per thread, f32x2 dot over D
    {
        const int l = tid & 15;
        const int rb = tid >> 4;
        const float bias = subb[l];
        const ulonglong2* wr = (const ulonglong2*)&ws[l][0];   // 32 x (2 f32x2) = 128 floats
#pragma unroll
        for (int it = 0; it < 4; it++) {
            const int r = rb + 16 * it;
            const ulonglong2* xr = (const ulonglong2*)&xs[r][0];
            unsigned long long acc = 0ULL;                      // (0.f, 0.f)
#pragma unroll
            for (int i = 0; i < 32; i++) {   // 32 iters x 4 floats = D=128 (full row)
                ulonglong2 a = xr[i], b = wr[i];
                FMA2(acc, a.x, b.x);
                FMA2(acc, a.y, b.y);
            }
            float lo, hi;
            asm("mov.b64 {%0, %1}, %2;" : "=f"(lo), "=f"(hi) : "l"(acc));
            const float s = lo + hi + bias;
            float v;
            const int m = l & 3;
            if (m == 0)      v = tanhf(s);
            else if (m == 1) v = fmaxf(s, 0.f);
            else if (m == 2) v = 1.f / (1.f + expf(-s));
            else             v = s;
            as_[r][l] = v;
        }
    }
    __syncthreads();

    // ---- aggregation: thread = (o-quad, 16-row group); agg_W quad in 64 regs
    {
        const int oq = tid & 63;          // o columns 4*oq .. 4*oq+3
        const int rq = tid >> 6;          // rows 16*rq .. 16*rq+15
        const int o0 = oq * 4;
        float4 wc[LL];
#pragma unroll
        for (int l = 0; l < LL; l++) wc[l] = *(const float4*)(aggW + l * OO + o0);

        float* outp = g_agg + (row0 + rq * 16) * (size_t)OO + o0;
#pragma unroll
        for (int rr = 0; rr < 16; rr++) {
            const int r = rq * 16 + rr;
            float ax = 0.f, ay = 0.f, az = 0.f, aw = 0.f;
#pragma unroll
            for (int l = 0; l < LL; l++) {
                const float a = as_[r][l];              // broadcast LDS
                ax += a * wc[l].x; ay += a * wc[l].y;
                az += a * wc[l].z; aw += a * wc[l].w;
            }
            float4 o4; o4.x = ax; o4.y = ay; o4.z = az; o4.w = aw;
            *(float4*)(outp + (size_t)rr * OO) = o4;    // coalesced STG.128
        }
    }
}

// ---------------------------------------------------------------------------
// Kernel 2: recurrence s_t = agg_t + s_{t-1} @ R  — R7 structure verbatim
// (best measured: 1013 us). Only diffs vs R7: branchless agg prefetch
// (padded g_agg) and pointer-incremented output stores.
// ---------------------------------------------------------------------------
__global__ void __launch_bounds__(NTHR, 1) recur_kernel(const float* __restrict__ R,
                                                        float* __restrict__ out)
{
    extern __shared__ unsigned char dyn[];
    unsigned int sm;
    asm("{ .reg .u64 t0; cvta.to.shared.u64 t0, %1; cvt.u32.u64 %0, t0; }"
        : "=r"(sm) : "l"(dyn));

    const int tid  = threadIdx.x;
    const int lane = tid & 31;
    const int w    = tid >> 5;
    const int c    = w & 3;        // k-chunk: rows 64c .. 64c+63
    const int h    = w >> 2;       // o-half
    const int b0   = blockIdx.x * 2;

    // ---- 24 k-pairs (48 rows) x 4 o-cols into registers
    unsigned long long Rp[24 * 4];
#pragma unroll
    for (int i = 0; i < 24; i++)
#pragma unroll
        for (int j = 0; j < 4; j++) {
            const int k = c * 64 + 2 * i;
            const int o = h * 128 + lane + 32 * j;
            float lo = R[(size_t)k * OO + o];
            float hi = R[(size_t)(k + 1) * OO + o];
            asm("mov.b64 %0, {%1, %2};" : "=l"(Rp[i * 4 + j]) : "f"(lo), "f"(hi));
        }

    // ---- 8 k-pairs (16 rows) x 4 o-cols into per-thread smem rows
    const unsigned int rsm = sm + RSM_OFF + tid * RSM_TSTRIDE;
#pragma unroll
    for (int i = 0; i < 8; i++)
#pragma unroll
        for (int j = 0; j < 4; j++) {
            const int k = c * 64 + 48 + 2 * i;
            const int o = h * 128 + lane + 32 * j;
            float lo = R[(size_t)k * OO + o];
            float hi = R[(size_t)(k + 1) * OO + o];
            unsigned long long p;
            asm("mov.b64 %0, {%1, %2};" : "=l"(p) : "f"(lo), "f"(hi));
            sts_u64(rsm + (unsigned)(i * 4 + j) * 8, p);
        }

    // zero initial state in buffer 0 (2 batches x 256)
    sts_f32(sm + S_OFF + 0 * 1024 + tid * 4, 0.f);
    sts_f32(sm + S_OFF + 1 * 1024 + tid * 4, 0.f);

    // phase-2 identity: thread -> output column o = tid, both batches
    const float* aggp0 = g_agg + ((size_t)b0       * TT) * OO + tid;
    const float* aggp1 = g_agg + ((size_t)(b0 + 1) * TT) * OO + tid;
    float*       outp0 = out   + ((size_t)b0       * TT) * OO + tid;
    float*       outp1 = out   + ((size_t)(b0 + 1) * TT) * OO + tid;
    float a0 = __ldg(aggp0), a1 = __ldg(aggp1);

    // addresses
    const unsigned int schunk = sm + S_OFF + c * 256;
    const unsigned int pw     = sm + PART_OFF + c * 2048 + (h * 128 + lane) * 4;
    const unsigned int pr     = sm + PART_OFF + tid * 4;
    const unsigned int sw     = sm + S_OFF + tid * 4;

    __syncthreads();

    for (int t = 0; t < TT; t++) {
        const int p = t & 1;
        // branchless prefetch of agg[t+1] (g_agg padded by one row)
        const float a0n = __ldg(aggp0 + (size_t)(t + 1) * OO);
        const float a1n = __ldg(aggp1 + (size_t)(t + 1) * OO);

        const unsigned int sA = schunk + p * 2048;
        const unsigned int sB = sA + 1024;

        unsigned long long acc0 = 0, acc1 = 0, acc2 = 0, acc3 = 0,
                           acc4 = 0, acc5 = 0, acc6 = 0, acc7 = 0;

        // -------- phase 1a: 24 register k-pairs --------
#pragma unroll
        for (int ii = 0; ii < 12; ii++) {
            unsigned long long ax, ay, bx, by;
            lds_v2u64(ax, ay, sA + ii * 16);
            lds_v2u64(bx, by, sB + ii * 16);
            FMA2(acc0, ax, Rp[(2*ii)*4+0]);   FMA2(acc4, bx, Rp[(2*ii)*4+0]);
            FMA2(acc1, ax, Rp[(2*ii)*4+1]);   FMA2(acc5, bx, Rp[(2*ii)*4+1]);
            FMA2(acc2, ax, Rp[(2*ii)*4+2]);   FMA2(acc6, bx, Rp[(2*ii)*4+2]);
            FMA2(acc3, ax, Rp[(2*ii)*4+3]);   FMA2(acc7, bx, Rp[(2*ii)*4+3]);
            FMA2(acc0, ay, Rp[(2*ii+1)*4+0]); FMA2(acc4, by, Rp[(2*ii+1)*4+0]);
            FMA2(acc1, ay, Rp[(2*ii+1)*4+1]); FMA2(acc5, by, Rp[(2*ii+1)*4+1]);
            FMA2(acc2, ay, Rp[(2*ii+1)*4+2]); FMA2(acc6, by, Rp[(2*ii+1)*4+2]);
            FMA2(acc3, ay, Rp[(2*ii+1)*4+3]); FMA2(acc7, by, Rp[(2*ii+1)*4+3]);
        }
        // -------- phase 1b: 8 smem k-pairs --------
#pragma unroll
        for (int q = 0; q < 4; q++) {
            unsigned long long ax, ay, bx, by;
            lds_v2u64(ax, ay, sA + (12 + q) * 16);
            lds_v2u64(bx, by, sB + (12 + q) * 16);
            unsigned long long r0, r1, r2, r3;
            lds_v2u64(r0, r1, rsm + (2*q) * 32);
            lds_v2u64(r2, r3, rsm + (2*q) * 32 + 16);
            FMA2(acc0, ax, r0); FMA2(acc4, bx, r0);
            FMA2(acc1, ax, r1); FMA2(acc5, bx, r1);
            FMA2(acc2, ax, r2); FMA2(acc6, bx, r2);
            FMA2(acc3, ax, r3); FMA2(acc7, bx, r3);
            lds_v2u64(r0, r1, rsm + (2*q+1) * 32);
            lds_v2u64(r2, r3, rsm + (2*q+1) * 32 + 16);
            FMA2(acc0, ay, r0); FMA2(acc4, by, r0);
            FMA2(acc1, ay, r1); FMA2(acc5, by, r1);
            FMA2(acc2, ay, r2); FMA2(acc6, by, r2);
            FMA2(acc3, ay, r3); FMA2(acc7, by, r3);
        }

        // combine even/odd-k halves, store 8 partials (coalesced STS.32)
        {
            float x, y;
            asm("mov.b64 {%0,%1}, %2;" : "=f"(x), "=f"(y) : "l"(acc0)); sts_f32(pw + 0*1024 + 0*128, x + y);
            asm("mov.b64 {%0,%1}, %2;" : "=f"(x), "=f"(y) : "l"(acc1)); sts_f32(pw + 0*1024 + 1*128, x + y);
            asm("mov.b64 {%0,%1}, %2;" : "=f"(x), "=f"(y) : "l"(acc2)); sts_f32(pw + 0*1024 + 2*128, x + y);
            asm("mov.b64 {%0,%1}, %2;" : "=f"(x), "=f"(y) : "l"(acc3)); sts_f32(pw + 0*1024 + 3*128, x + y);
            asm("mov.b64 {%0,%1}, %2;" : "=f"(x), "=f"(y) : "l"(acc4)); sts_f32(pw + 1*1024 + 0*128, x + y);
            asm("mov.b64 {%0,%1}, %2;" : "=f"(x), "=f"(y) : "l"(acc5)); sts_f32(pw + 1*1024 + 1*128, x + y);
            asm("mov.b64 {%0,%1}, %2;" : "=f"(x), "=f"(y) : "l"(acc6)); sts_f32(pw + 1*1024 + 2*128, x + y);
            asm("mov.b64 {%0,%1}, %2;" : "=f"(x), "=f"(y) : "l"(acc7)); sts_f32(pw + 1*1024 + 3*128, x + y);
        }
        __syncthreads();

        // -------- phase 2: reduce 4 chunk-partials per (o,batch), publish --------
        float r0 = a0 + lds_f32(pr + 0*2048)
                      + lds_f32(pr + 1*2048)
                      + lds_f32(pr + 2*2048)
                      + lds_f32(pr + 3*2048);
        float r1 = a1 + lds_f32(pr + 0*2048 + 1024)
                      + lds_f32(pr + 1*2048 + 1024)
                      + lds_f32(pr + 2*2048 + 1024)
                      + lds_f32(pr + 3*2048 + 1024);
        const unsigned int swp = sw + (p ^ 1) * 2048;
        sts_f32(swp, r0);
        sts_f32(swp + 1024, r1);
        *outp0 = r0;
        *outp1 = r1;
        outp0 += OO;
        outp1 += OO;

        a0 = a0n; a1 = a1n;
        __syncthreads();
    }
}

// ---------------------------------------------------------------------------
extern "C" void kernel_launch(void* const* d_in, const int* in_sizes, int n_in,
                              void* d_out, int out_size)
{
    const float* x    = (const float*)d_in[0];
    const float* subW = (const float*)d_in[1];
    const float* subb = (const float*)d_in[2];
    const float* aggW = (const float*)d_in[3];
    const float* R    = (const float*)d_in[4];
    float* out = (float*)d_out;

    cudaFuncSetAttribute(recur_kernel, cudaFuncAttributeMaxDynamicSharedMemorySize,
                         SMEM_BYTES);

    act_agg_kernel<<<(BB * TT) / 64, 256>>>(x, subW, subb, aggW);
    recur_kernel<<<BB / 2, NTHR, SMEM_BYTES>>>(R, out);
}